// round 12
// baseline (speedup 1.0000x reference)
#include <cuda_runtime.h>
#include <stdint.h>

// YOLO loss, persistent kernel, 3-deep cp.async pipeline on pred.
// tbox+mask prefetched one tile ahead in registers; tcls loads predicated on
// mask (fm==0 lanes skip, ~36MB traffic saved) and issued early in the
// iteration so their latency hides under the IoU math.
// Output: 5 f32 [total, reg, contain, noobj, cls] / N.

#define SGRID 28
#define TPB   128
#define WPB   (TPB / 32)
#define DEPTH 3
#define L_COORD 5.0
#define L_NOOBJ 0.5

__device__ double       g_acc[4] = {0.0, 0.0, 0.0, 0.0};  // cls, noobj, reg, contain
__device__ unsigned int g_count  = 0;

__device__ __forceinline__ void cp16(uint32_t dst, const void* src) {
    asm volatile("cp.async.cg.shared.global [%0], [%1], 16;" :: "r"(dst), "l"(src));
}

__device__ __forceinline__ float iou_vs_t(float bcx, float bcy, float bw, float bh,
                                          float t0, float t1, float t2, float t3) {
    const float invS = 1.0f / (float)SGRID;
    float bx = bcx * invS, by = bcy * invS;
    float b0 = bx - 0.5f * bw, b1 = by - 0.5f * bh;
    float b2 = bx + 0.5f * bw, b3 = by + 0.5f * bh;
    float lt0 = fmaxf(b0, t0), lt1 = fmaxf(b1, t1);
    float rb0 = fminf(b2, t2), rb1 = fminf(b3, t3);
    float w = fmaxf(rb0 - lt0, 0.0f), h = fmaxf(rb1 - lt1, 0.0f);
    float inter = w * h;
    float a1 = (b2 - b0) * (b3 - b1);
    float a2 = (t2 - t0) * (t3 - t1);
    float denom = a1 + a2 - inter;
    return inter / (denom > 0.0f ? denom : 1.0f);
}

__global__ void __launch_bounds__(TPB)
yolo_fused(const float* __restrict__ pred,
           const float* __restrict__ tbox,
           const float* __restrict__ tcls,
           const void*  __restrict__ mask,
           int ncells, int ntiles,
           float* __restrict__ out, double invN) {
    __shared__ float  s_pred[WPB * DEPTH * 960];   // 45 KB
    __shared__ float4 s_red[WPB];
    __shared__ int    s_last;

    const int tid = threadIdx.x;
    const int lid = tid & 31;
    const int wid = tid >> 5;

    if (tid == 0) s_last = 0;

    // ---- mask dtype detection: per-warp, 512B L2-hot, pure bit ops ----
    // f32 1.0 has bytes >1; int32 0/1 has nonzero bytes only at off%4==0.
    bool four_byte;
    {
        uint4 v = ((const uint4*)mask)[lid];           // mask buffer >= 784 B
        unsigned int a = v.x | v.y | v.z | v.w;
        int gt1 = __any_sync(0xFFFFFFFFu, (a & 0xFEFEFEFEu) != 0u);
        int off = __any_sync(0xFFFFFFFFu, (a & 0xFFFFFF00u) != 0u);
        four_byte = (gt1 != 0) || (off == 0);
    }

    float* wbuf = s_pred + wid * (DEPTH * 960);
    const int W = gridDim.x * WPB;                 // total warps in grid
    const int wstart = blockIdx.x * WPB + wid;

    // stage pred for tile t into slot s; ALWAYS exactly one commit group
    auto stage = [&](int t, int s) {
        if (t < ntiles) {
            float* sf = wbuf + s * 960;
            uint32_t sb = (uint32_t)__cvta_generic_to_shared(sf);
            int base = t * 32;
            int wcnt = min(32, ncells - base);
            if (wcnt == 32) {
                const uint4* gp = (const uint4*)(pred + (size_t)base * 30);
                #pragma unroll
                for (int k = 0; k < 7; k++)
                    cp16(sb + (uint32_t)(lid + k * 32) * 16u, gp + lid + k * 32);
                if (lid < 16)
                    cp16(sb + (uint32_t)(224 + lid) * 16u, gp + 224 + lid);
            } else {
                for (int e = lid; e < wcnt * 30; e += 32)
                    sf[e] = pred[(size_t)base * 30 + e];
            }
        }
        asm volatile("cp.async.commit_group;");
    };
    // register prefetch of tbox + mask for tile t
    auto pfetch = [&](int t, float4& ptb, float& pfm) {
        int c = t * 32 + lid;
        if (t < ntiles && c < ncells) {
            ptb = __ldg((const float4*)tbox + c);
            if (four_byte) pfm = (((const unsigned int*)mask)[c] != 0u) ? 1.0f : 0.0f;
            else           pfm = (((const unsigned char*)mask)[c] != 0)  ? 1.0f : 0.0f;
        }
    };

    float acls = 0.0f, ano = 0.0f, areg = 0.0f, act = 0.0f;

    float4 pf_tb = make_float4(0.f, 0.f, 0.f, 0.f);
    float  pf_fm = 0.0f;

    // prologue: fill DEPTH slots (empty commits keep group count uniform)
    stage(wstart,         0);
    stage(wstart + W,     1);
    stage(wstart + 2 * W, 2);
    pfetch(wstart, pf_tb, pf_fm);

    int slot = 0;
    for (int t = wstart; t < ntiles; t += W) {
        asm volatile("cp.async.wait_group %0;" :: "n"(DEPTH - 1) : "memory");
        __syncwarp();

        float4 tb = pf_tb;
        float  fm = pf_fm;
        pfetch(t + W, pf_tb, pf_fm);                   // overlaps compute

        const float* sp = wbuf + slot * 960;
        const int base = t * 32;
        const int wcnt = min(32, ncells - base);

        if (lid < wcnt) {
            const int c = base + lid;
            const float2* P2 = (const float2*)(sp + lid * 30);
            const bool on = fm > 0.0f;

            // issue tcls loads FIRST (predicated); consumed after the IoU math
            float4 c0, c1, c2, c3, c4;
            if (on) {
                const float4* C4 = (const float4*)(tcls + (size_t)c * 20);
                c0 = __ldg(C4 + 0); c1 = __ldg(C4 + 1); c2 = __ldg(C4 + 2);
                c3 = __ldg(C4 + 3); c4 = __ldg(C4 + 4);
            }

            float2 p01 = P2[0], p23 = P2[1], p45 = P2[2], p67 = P2[3], p89 = P2[4];

            ano += (1.0f - fm) * (p45.x * p45.x + p89.y * p89.y);  // raw; x0.5 later

            const float invS = 1.0f / (float)SGRID;
            float tx = tb.x * invS, ty = tb.y * invS;
            float t0 = tx - 0.5f * tb.z, t1 = ty - 0.5f * tb.w;
            float t2 = tx + 0.5f * tb.z, t3 = ty + 0.5f * tb.w;

            // box1=(p01.x,p01.y,p23.x,p23.y,p45.x) box2=(p45.y,p67.x,p67.y,p89.x,p89.y)
            float i1 = iou_vs_t(p01.x, p01.y, p23.x, p23.y, t0, t1, t2, t3);
            float i2 = iou_vs_t(p45.y, p67.x, p67.y, p89.x, t0, t1, t2, t3);
            bool take1 = i1 > i2;
            float bx0 = take1 ? p01.x : p45.y;
            float bx1 = take1 ? p01.y : p67.x;
            float bx2 = take1 ? p23.x : p67.y;
            float bx3 = take1 ? p23.y : p89.x;
            float bx4 = take1 ? p45.x : p89.y;
            float best_iou = take1 ? i1 : i2;

            float dx = bx0 - tb.x, dy = bx1 - tb.y;
            float xy = dx * dx + dy * dy;

            float dw = sqrtf(on ? bx2 : 1.0f) - sqrtf(on ? tb.z : 1.0f);
            float dh = sqrtf(on ? bx3 : 1.0f) - sqrtf(on ? tb.w : 1.0f);
            areg += fm * (xy + dw * dw + dh * dh);                 // raw; x5 later

            float dc = bx4 - best_iou;
            act += fm * dc * dc;

            // classification loss — tcls regs now long since landed
            if (on) {
                float2 qa, qb; float cls = 0.0f, d0, d1, d2, d3;
                qa = P2[5];  qb = P2[6];
                d0 = qa.x - c0.x; d1 = qa.y - c0.y; d2 = qb.x - c0.z; d3 = qb.y - c0.w;
                cls = fmaf(d0, d0, cls); cls = fmaf(d1, d1, cls);
                cls = fmaf(d2, d2, cls); cls = fmaf(d3, d3, cls);
                qa = P2[7];  qb = P2[8];
                d0 = qa.x - c1.x; d1 = qa.y - c1.y; d2 = qb.x - c1.z; d3 = qb.y - c1.w;
                cls = fmaf(d0, d0, cls); cls = fmaf(d1, d1, cls);
                cls = fmaf(d2, d2, cls); cls = fmaf(d3, d3, cls);
                qa = P2[9];  qb = P2[10];
                d0 = qa.x - c2.x; d1 = qa.y - c2.y; d2 = qb.x - c2.z; d3 = qb.y - c2.w;
                cls = fmaf(d0, d0, cls); cls = fmaf(d1, d1, cls);
                cls = fmaf(d2, d2, cls); cls = fmaf(d3, d3, cls);
                qa = P2[11]; qb = P2[12];
                d0 = qa.x - c3.x; d1 = qa.y - c3.y; d2 = qb.x - c3.z; d3 = qb.y - c3.w;
                cls = fmaf(d0, d0, cls); cls = fmaf(d1, d1, cls);
                cls = fmaf(d2, d2, cls); cls = fmaf(d3, d3, cls);
                qa = P2[13]; qb = P2[14];
                d0 = qa.x - c4.x; d1 = qa.y - c4.y; d2 = qb.x - c4.z; d3 = qb.y - c4.w;
                cls = fmaf(d0, d0, cls); cls = fmaf(d1, d1, cls);
                cls = fmaf(d2, d2, cls); cls = fmaf(d3, d3, cls);
                acls += cls;                            // fm==1 here
            }
        }
        __syncwarp();                 // all lanes done before slot restaged
        stage(t + DEPTH * W, slot);   // refill this slot (or empty commit)
        slot = (slot + 1) % DEPTH;
    }

    // ---- reduce: warp shuffles -> smem -> fp64 atomics ----
    #pragma unroll
    for (int o = 16; o > 0; o >>= 1) {
        acls += __shfl_down_sync(0xFFFFFFFFu, acls, o);
        ano  += __shfl_down_sync(0xFFFFFFFFu, ano,  o);
        areg += __shfl_down_sync(0xFFFFFFFFu, areg, o);
        act  += __shfl_down_sync(0xFFFFFFFFu, act,  o);
    }
    if (lid == 0) s_red[wid] = make_float4(acls, ano, areg, act);
    __syncthreads();
    if (tid == 0) {
        float4 v = s_red[0];
        #pragma unroll
        for (int w = 1; w < WPB; w++) {
            v.x += s_red[w].x; v.y += s_red[w].y;
            v.z += s_red[w].z; v.w += s_red[w].w;
        }
        atomicAdd(&g_acc[0], (double)v.x);
        atomicAdd(&g_acc[1], (double)v.y);
        atomicAdd(&g_acc[2], (double)v.z);
        atomicAdd(&g_acc[3], (double)v.w);
        __threadfence();
        unsigned int done = atomicAdd(&g_count, 1u);
        if (done == gridDim.x - 1u) s_last = 1;
    }
    __syncthreads();

    // ---- last block finalizes and resets for next graph replay ----
    if (s_last && tid == 0) {
        double cls = g_acc[0];
        double no  = L_NOOBJ * g_acc[1];
        double reg = L_COORD * g_acc[2];
        double ct  = g_acc[3];
        double tot = cls + no + reg + ct;
        out[0] = (float)(tot * invN);
        out[1] = (float)(reg * invN);
        out[2] = (float)(ct  * invN);
        out[3] = (float)(no  * invN);
        out[4] = (float)(cls * invN);
        g_acc[0] = 0.0; g_acc[1] = 0.0; g_acc[2] = 0.0; g_acc[3] = 0.0;
        g_count = 0;
    }
}

extern "C" void kernel_launch(void* const* d_in, const int* in_sizes, int n_in,
                              void* d_out, int out_size) {
    const float* pred = (const float*)d_in[0];
    const float* tbox = (const float*)d_in[1];
    const float* tcls = (const float*)d_in[2];
    const void*  mask = d_in[3];

    int ncells = in_sizes[0] / 30;               // N*28*28
    int nbatch = ncells / (SGRID * SGRID);       // N
    double invN = 1.0 / (double)nbatch;
    int ntiles = (ncells + 31) / 32;             // 25088 for N=1024

    int nblocks = 148 * 4;                       // one wave at 4 blocks/SM (45KB smem)
    int maxb = (ntiles + WPB - 1) / WPB;
    if (nblocks > maxb) nblocks = maxb;

    yolo_fused<<<nblocks, TPB>>>(pred, tbox, tcls, mask, ncells, ntiles,
                                 (float*)d_out, invN);
}

// round 15
// speedup vs baseline: 1.0313x; 1.0313x over previous
#include <cuda_runtime.h>
#include <stdint.h>

// YOLO loss, persistent kernel, 3-deep cp.async pipeline staging ONLY the
// per-cell box region (floats 0..9) via paired 16B chunks (112B/pair in smem,
// 16B-aligned dst). pred_cls + tcls loaded predicated on mask. tbox+mask
// prefetched one tile ahead in registers.
// Output: 5 f32 [total, reg, contain, noobj, cls] / N.

#define SGRID 28
#define TPB   256
#define WPB   (TPB / 32)
#define DEPTH 3
#define PAIRF 28                 // floats per staged pair (112 B, 16B-aligned)
#define SLOTF (16 * PAIRF)       // floats per tile slot (448 f = 1792 B)
#define L_COORD 5.0
#define L_NOOBJ 0.5

__device__ double       g_acc[4] = {0.0, 0.0, 0.0, 0.0};  // cls, noobj, reg, contain
__device__ unsigned int g_count  = 0;

__device__ __forceinline__ void cp16(uint32_t dst, const void* src) {
    asm volatile("cp.async.cg.shared.global [%0], [%1], 16;" :: "r"(dst), "l"(src));
}

__device__ __forceinline__ float iou_vs_t(float bcx, float bcy, float bw, float bh,
                                          float t0, float t1, float t2, float t3) {
    const float invS = 1.0f / (float)SGRID;
    float bx = bcx * invS, by = bcy * invS;
    float b0 = bx - 0.5f * bw, b1 = by - 0.5f * bh;
    float b2 = bx + 0.5f * bw, b3 = by + 0.5f * bh;
    float lt0 = fmaxf(b0, t0), lt1 = fmaxf(b1, t1);
    float rb0 = fminf(b2, t2), rb1 = fminf(b3, t3);
    float w = fmaxf(rb0 - lt0, 0.0f), h = fmaxf(rb1 - lt1, 0.0f);
    float inter = w * h;
    float a1 = (b2 - b0) * (b3 - b1);
    float a2 = (t2 - t0) * (t3 - t1);
    float denom = a1 + a2 - inter;
    return inter / (denom > 0.0f ? denom : 1.0f);
}

__global__ void __launch_bounds__(TPB, 3)
yolo_fused(const float* __restrict__ pred,
           const float* __restrict__ tbox,
           const float* __restrict__ tcls,
           const void*  __restrict__ mask,
           int ncells, int ntiles,
           float* __restrict__ out, double invN) {
    __shared__ float  s_box[WPB * DEPTH * SLOTF];   // 42 KB
    __shared__ float4 s_red[WPB];
    __shared__ int    s_last;

    const int tid = threadIdx.x;
    const int lid = tid & 31;
    const int wid = tid >> 5;

    if (tid == 0) s_last = 0;

    // ---- mask dtype detection: per-warp, 512B L2-hot, pure bit ops ----
    // f32 1.0 has bytes >1; int32 0/1 has nonzero bytes only at off%4==0.
    bool four_byte;
    {
        uint4 v = ((const uint4*)mask)[lid];           // mask buffer >= 784 B
        unsigned int a = v.x | v.y | v.z | v.w;
        int gt1 = __any_sync(0xFFFFFFFFu, (a & 0xFEFEFEFEu) != 0u);
        int off = __any_sync(0xFFFFFFFFu, (a & 0xFFFFFF00u) != 0u);
        four_byte = (gt1 != 0) || (off == 0);
    }

    float* wbuf = s_box + wid * (DEPTH * SLOTF);
    const int W = gridDim.x * WPB;                 // total warps in grid
    const int wstart = blockIdx.x * WPB + wid;

    // stage box floats 0..9 of 32 cells (16 pairs) for tile t into slot s.
    // pair q (cells 2q,2q+1) = gmem bytes [240q,240q+240); box regions covered
    // by six aligned 16B chunks: src [0,48) and [112,160).
    // chunk k = 6q+s_: src byte 240q + 16s_ + (s_>=3 ? 64 : 0)    (16B-aligned)
    //                  dst byte 112q + 16s_                        (16B-aligned)
    // cell 2q   box floats at dst float ofs 28q + 0..9
    // cell 2q+1 box floats at dst float ofs 28q + 14..23
    // ALWAYS exactly one commit group.
    auto stage = [&](int t, int s) {
        if (t < ntiles) {
            float* sf = wbuf + s * SLOTF;
            uint32_t sb = (uint32_t)__cvta_generic_to_shared(sf);
            int base = t * 32;
            int wcnt = min(32, ncells - base);      // even (ncells, base even)
            if (wcnt == 32) {
                const char* gb = (const char*)(pred + (size_t)base * 30);
                #pragma unroll
                for (int r = 0; r < 3; r++) {
                    int k  = lid + r * 32;          // 0..95
                    int q  = (k * 43691) >> 18;     // k/6 for small k
                    int s_ = k - 6 * q;
                    uint32_t srcb = (uint32_t)(240 * q + 16 * s_ + ((s_ >= 3) ? 64 : 0));
                    uint32_t dstb = (uint32_t)(112 * q + 16 * s_);
                    cp16(sb + dstb, gb + srcb);
                }
            } else {
                for (int c2 = lid; c2 < wcnt; c2 += 32) {
                    const float* g = pred + (size_t)(base + c2) * 30;
                    float* d = sf + PAIRF * (c2 >> 1) + (c2 & 1) * 14;
                    #pragma unroll
                    for (int f = 0; f < 10; f++) d[f] = g[f];
                }
            }
        }
        asm volatile("cp.async.commit_group;");
    };
    // register prefetch of tbox + mask for tile t
    auto pfetch = [&](int t, float4& ptb, float& pfm) {
        int c = t * 32 + lid;
        if (t < ntiles && c < ncells) {
            ptb = __ldg((const float4*)tbox + c);
            if (four_byte) pfm = (((const unsigned int*)mask)[c] != 0u) ? 1.0f : 0.0f;
            else           pfm = (((const unsigned char*)mask)[c] != 0)  ? 1.0f : 0.0f;
        }
    };

    float acls = 0.0f, ano = 0.0f, areg = 0.0f, act = 0.0f;

    float4 pf_tb = make_float4(0.f, 0.f, 0.f, 0.f);
    float  pf_fm = 0.0f;

    // prologue
    stage(wstart,         0);
    stage(wstart + W,     1);
    stage(wstart + 2 * W, 2);
    pfetch(wstart, pf_tb, pf_fm);

    int slot = 0;
    for (int t = wstart; t < ntiles; t += W) {
        asm volatile("cp.async.wait_group %0;" :: "n"(DEPTH - 1) : "memory");
        __syncwarp();

        float4 tb = pf_tb;
        float  fm = pf_fm;
        pfetch(t + W, pf_tb, pf_fm);                   // overlaps compute

        const float* sp = wbuf + slot * SLOTF;
        const int base = t * 32;
        const int wcnt = min(32, ncells - base);

        if (lid < wcnt) {
            const int c = base + lid;
            const bool on = fm > 0.0f;

            // predicated gmem loads issued FIRST; consumed after IoU math
            float2 pc0, pc1, pc2, pc3, pc4, pc5, pc6, pc7, pc8, pc9;
            float4 c0, c1, c2, c3, c4;
            if (on) {
                const float2* G = (const float2*)(pred + (size_t)c * 30 + 10);
                pc0 = __ldg(G + 0); pc1 = __ldg(G + 1); pc2 = __ldg(G + 2);
                pc3 = __ldg(G + 3); pc4 = __ldg(G + 4); pc5 = __ldg(G + 5);
                pc6 = __ldg(G + 6); pc7 = __ldg(G + 7); pc8 = __ldg(G + 8);
                pc9 = __ldg(G + 9);
                const float4* C4 = (const float4*)(tcls + (size_t)c * 20);
                c0 = __ldg(C4 + 0); c1 = __ldg(C4 + 1); c2 = __ldg(C4 + 2);
                c3 = __ldg(C4 + 3); c4 = __ldg(C4 + 4);
            }

            // box floats 0..9 from staged smem (8B-aligned)
            const float2* B2 = (const float2*)(sp + PAIRF * (lid >> 1) + (lid & 1) * 14);
            float2 p01 = B2[0], p23 = B2[1], p45 = B2[2], p67 = B2[3], p89 = B2[4];

            ano += (1.0f - fm) * (p45.x * p45.x + p89.y * p89.y);  // raw; x0.5 later

            const float invS = 1.0f / (float)SGRID;
            float tx = tb.x * invS, ty = tb.y * invS;
            float t0 = tx - 0.5f * tb.z, t1 = ty - 0.5f * tb.w;
            float t2 = tx + 0.5f * tb.z, t3 = ty + 0.5f * tb.w;

            // box1=(p01.x,p01.y,p23.x,p23.y,p45.x) box2=(p45.y,p67.x,p67.y,p89.x,p89.y)
            float i1 = iou_vs_t(p01.x, p01.y, p23.x, p23.y, t0, t1, t2, t3);
            float i2 = iou_vs_t(p45.y, p67.x, p67.y, p89.x, t0, t1, t2, t3);
            bool take1 = i1 > i2;
            float bx0 = take1 ? p01.x : p45.y;
            float bx1 = take1 ? p01.y : p67.x;
            float bx2 = take1 ? p23.x : p67.y;
            float bx3 = take1 ? p23.y : p89.x;
            float bx4 = take1 ? p45.x : p89.y;
            float best_iou = take1 ? i1 : i2;

            float dx = bx0 - tb.x, dy = bx1 - tb.y;
            float xy = dx * dx + dy * dy;

            float dw = sqrtf(on ? bx2 : 1.0f) - sqrtf(on ? tb.z : 1.0f);
            float dh = sqrtf(on ? bx3 : 1.0f) - sqrtf(on ? tb.w : 1.0f);
            areg += fm * (xy + dw * dw + dh * dh);                 // raw; x5 later

            float dc = bx4 - best_iou;
            act += fm * dc * dc;

            // classification loss — loads long since landed
            if (on) {
                float cls = 0.0f, d0, d1, d2, d3;
                d0 = pc0.x - c0.x; d1 = pc0.y - c0.y; d2 = pc1.x - c0.z; d3 = pc1.y - c0.w;
                cls = fmaf(d0, d0, cls); cls = fmaf(d1, d1, cls);
                cls = fmaf(d2, d2, cls); cls = fmaf(d3, d3, cls);
                d0 = pc2.x - c1.x; d1 = pc2.y - c1.y; d2 = pc3.x - c1.z; d3 = pc3.y - c1.w;
                cls = fmaf(d0, d0, cls); cls = fmaf(d1, d1, cls);
                cls = fmaf(d2, d2, cls); cls = fmaf(d3, d3, cls);
                d0 = pc4.x - c2.x; d1 = pc4.y - c2.y; d2 = pc5.x - c2.z; d3 = pc5.y - c2.w;
                cls = fmaf(d0, d0, cls); cls = fmaf(d1, d1, cls);
                cls = fmaf(d2, d2, cls); cls = fmaf(d3, d3, cls);
                d0 = pc6.x - c3.x; d1 = pc6.y - c3.y; d2 = pc7.x - c3.z; d3 = pc7.y - c3.w;
                cls = fmaf(d0, d0, cls); cls = fmaf(d1, d1, cls);
                cls = fmaf(d2, d2, cls); cls = fmaf(d3, d3, cls);
                d0 = pc8.x - c4.x; d1 = pc8.y - c4.y; d2 = pc9.x - c4.z; d3 = pc9.y - c4.w;
                cls = fmaf(d0, d0, cls); cls = fmaf(d1, d1, cls);
                cls = fmaf(d2, d2, cls); cls = fmaf(d3, d3, cls);
                acls += cls;                            // fm==1 here
            }
        }
        __syncwarp();                 // all lanes done before slot restaged
        stage(t + DEPTH * W, slot);
        slot = (slot + 1) % DEPTH;
    }

    // ---- reduce: warp shuffles -> smem -> fp64 atomics ----
    #pragma unroll
    for (int o = 16; o > 0; o >>= 1) {
        acls += __shfl_down_sync(0xFFFFFFFFu, acls, o);
        ano  += __shfl_down_sync(0xFFFFFFFFu, ano,  o);
        areg += __shfl_down_sync(0xFFFFFFFFu, areg, o);
        act  += __shfl_down_sync(0xFFFFFFFFu, act,  o);
    }
    if (lid == 0) s_red[wid] = make_float4(acls, ano, areg, act);
    __syncthreads();
    if (tid == 0) {
        float4 v = s_red[0];
        #pragma unroll
        for (int w = 1; w < WPB; w++) {
            v.x += s_red[w].x; v.y += s_red[w].y;
            v.z += s_red[w].z; v.w += s_red[w].w;
        }
        atomicAdd(&g_acc[0], (double)v.x);
        atomicAdd(&g_acc[1], (double)v.y);
        atomicAdd(&g_acc[2], (double)v.z);
        atomicAdd(&g_acc[3], (double)v.w);
        __threadfence();
        unsigned int done = atomicAdd(&g_count, 1u);
        if (done == gridDim.x - 1u) s_last = 1;
    }
    __syncthreads();

    // ---- last block finalizes and resets for next graph replay ----
    if (s_last && tid == 0) {
        double cls = g_acc[0];
        double no  = L_NOOBJ * g_acc[1];
        double reg = L_COORD * g_acc[2];
        double ct  = g_acc[3];
        double tot = cls + no + reg + ct;
        out[0] = (float)(tot * invN);
        out[1] = (float)(reg * invN);
        out[2] = (float)(ct  * invN);
        out[3] = (float)(no  * invN);
        out[4] = (float)(cls * invN);
        g_acc[0] = 0.0; g_acc[1] = 0.0; g_acc[2] = 0.0; g_acc[3] = 0.0;
        g_count = 0;
    }
}

extern "C" void kernel_launch(void* const* d_in, const int* in_sizes, int n_in,
                              void* d_out, int out_size) {
    const float* pred = (const float*)d_in[0];
    const float* tbox = (const float*)d_in[1];
    const float* tcls = (const float*)d_in[2];
    const void*  mask = d_in[3];

    int ncells = in_sizes[0] / 30;               // N*28*28 (even)
    int nbatch = ncells / (SGRID * SGRID);       // N
    double invN = 1.0 / (double)nbatch;
    int ntiles = (ncells + 31) / 32;             // 25088 for N=1024

    int nblocks = 148 * 3;                       // one wave at 3 blocks/SM
    int maxb = (ntiles + WPB - 1) / WPB;
    if (nblocks > maxb) nblocks = maxb;

    yolo_fused<<<nblocks, TPB>>>(pred, tbox, tcls, mask, ncells, ntiles,
                                 (float*)d_out, invN);
}